// round 9
// baseline (speedup 1.0000x reference)
#include <cuda_runtime.h>
#include <cstddef>

#define BATCH 512
#define TT    512
#define DD    128
#define DOUTN 32
#define CCLS  4
#define TBLK  32
#define XPITCH 33
#define NW    2           // warps per block

#define ALPHA_C 0.1f
#define GAMMA_C 0.9f
#define EPS_C   1e-5f
#define EPSH_C  1e-6f
#define LNEPS_C 1e-5f

__device__ __forceinline__ float warp_sum(float v) {
#pragma unroll
    for (int s = 16; s > 0; s >>= 1)
        v += __shfl_xor_sync(0xffffffffu, v, s, 32);
    return v;
}

__device__ __forceinline__ unsigned long long fma2(unsigned long long a,
                                                   unsigned long long b,
                                                   unsigned long long c) {
    unsigned long long d;
    asm("fma.rn.f32x2 %0, %1, %2, %3;" : "=l"(d) : "l"(a), "l"(b), "l"(c));
    return d;
}

__device__ __forceinline__ unsigned long long add2(unsigned long long a,
                                                   unsigned long long b) {
    unsigned long long d;
    asm("add.rn.f32x2 %0, %1, %2;" : "=l"(d) : "l"(a), "l"(b));
    return d;
}

__device__ __forceinline__ unsigned long long pack2(float lo, float hi) {
    unsigned long long r;
    asm("mov.b64 %0, {%1, %2};" : "=l"(r) : "f"(lo), "f"(hi));
    return r;
}

__device__ __forceinline__ void unpack2(unsigned long long v, float& lo, float& hi) {
    asm("mov.b64 {%0, %1}, %2;" : "=f"(lo), "=f"(hi) : "l"(v));
}

__global__ __launch_bounds__(64, 1)
void sync_head_kernel(const float* __restrict__ z_ticks,
                      const float* __restrict__ proj,
                      const float* __restrict__ ln_w,
                      const float* __restrict__ ln_b,
                      const float* __restrict__ cls_w,
                      const float* __restrict__ cls_b,
                      float* __restrict__ out_x,
                      float* __restrict__ out_logits) {
    __shared__ __align__(16) float sZ[2][NW][2][DD];        // [buf][warp][chain][d]
    __shared__ float4 cst[TT];
    __shared__ float itab[TT + 1];
    __shared__ __align__(16) float A[DOUTN][CCLS];
    __shared__ float4 SaV, SbV;
    __shared__ float xbuf[NW][2][DOUTN * XPITCH];

    const int lane = threadIdx.x & 31;
    const int w    = threadIdx.x >> 5;
    const int batchA = blockIdx.x * 4 + w * 2;
    const int batchB = batchA + 1;

    for (int t = threadIdx.x; t <= TT; t += 64) {
        float tau = (float)(t + 1);
        itab[t] = 1.0f / tau;
        if (t < TT) {
            float denom = fmaxf(tau - 1.0f, 1.0f);
            float inv_denom = 1.0f / denom;
            float g = __powf(GAMMA_C, tau);
            float s = (1.0f - g) / (1.0f - GAMMA_C);
            cst[t] = make_float4(0.0f,
                                 ALPHA_C * inv_denom * (1.0f / 128.0f),
                                 (1.0f - ALPHA_C) * inv_denom,
                                 1.0f / s);
        }
    }
    {
        // DOUTN*CCLS = 128 entries, 64 threads -> 2 each
        for (int i = threadIdx.x; i < DOUTN * CCLS; i += 64) {
            int j = i >> 2, c = i & 3;
            A[j][c] = ln_w[j] * cls_w[c * DOUTN + j];
        }
    }
    if (threadIdx.x < 2 * CCLS) {
        int c = threadIdx.x & 3;
        float acc = 0.f;
        if (threadIdx.x < CCLS) {
            for (int j = 0; j < DOUTN; j++) acc += ln_w[j] * cls_w[c * DOUTN + j];
            ((float*)&SaV)[c] = acc;
        } else {
            for (int j = 0; j < DOUTN; j++) acc += ln_b[j] * cls_w[c * DOUTN + j];
            ((float*)&SbV)[c] = acc + cls_b[c];
        }
    }

    // ---- proj column `lane` in registers (shared by both chains) ----
    unsigned long long q[DD / 2];
#pragma unroll
    for (int i = 0; i < DD / 2; i++) {
        float a = proj[(2 * i) * DOUTN + lane];
        float b = proj[(2 * i + 1) * DOUTN + lane];
        q[i] = pack2(a, b);
    }

    __syncthreads();
    const float4 Sa4 = SaV;
    const float4 Sb4 = SbV;

    const float* zA = z_ticks + (size_t)batchA * TT * DD + lane * 4;
    const float* zB = z_ticks + (size_t)batchB * TT * DD + lane * 4;
    float* oxA  = out_x + ((size_t)batchA * TT) * DOUTN + lane;
    float* oxB  = out_x + ((size_t)batchB * TT) * DOUTN + lane;
    float* olA  = out_logits + (size_t)batchA * TT * CCLS;
    float* olB  = out_logits + (size_t)batchB * TT * CCLS;
    float* xbA  = xbuf[w][0];
    float* xbB  = xbuf[w][1];

    // ---- preamble: state after step 0; z_tilde_0 = 0 ----
    float4 zA0 = *(const float4*)(zA);
    float4 zB0 = *(const float4*)(zB);
    float mA0 = zA0.x, mA1 = zA0.y, mA2 = zA0.z, mA3 = zA0.w;
    float mB0 = zB0.x, mB1 = zB0.y, mB2 = zB0.z, mB3 = zB0.w;
    float sA0 = 0.f, sA1 = 0.f, sA2 = 0.f, sA3 = 0.f;
    float sB0 = 0.f, sB1 = 0.f, sB2 = 0.f, sB3 = 0.f;
    float hA = 0.f, hB = 0.f;
    float cw = cst[0].w;

    ((float4*)sZ[0][w][0])[lane] = make_float4(0.f, 0.f, 0.f, 0.f);
    ((float4*)sZ[0][w][1])[lane] = make_float4(0.f, 0.f, 0.f, 0.f);
    __syncwarp();

    float4 zAb0 = *(const float4*)(zA + DD);
    float4 zAb1 = *(const float4*)(zA + 2 * DD);
    float4 zBb0 = *(const float4*)(zB + DD);
    float4 zBb1 = *(const float4*)(zB + 2 * DD);

#pragma unroll 1
    for (int t = 0; t < TT; t++) {
        // ---- Welford for step t+1, both chains ----
        const float4 za = zAb0;  zAb0 = zAb1;
        const float4 zb = zBb0;  zBb0 = zBb1;
        {
            int tp = t + 3; if (tp > TT - 1) tp = TT - 1;
            zAb1 = *(const float4*)(zA + (size_t)tp * DD);
            zBb1 = *(const float4*)(zB + (size_t)tp * DD);
        }
        const float itn = itab[t + 1];

        float dA0 = za.x - mA0, dA1 = za.y - mA1, dA2 = za.z - mA2, dA3 = za.w - mA3;
        float dB0 = zb.x - mB0, dB1 = zb.y - mB1, dB2 = zb.z - mB2, dB3 = zb.w - mB3;
        float eA0 = fmaf(-dA0, itn, dA0), eA1 = fmaf(-dA1, itn, dA1);
        float eA2 = fmaf(-dA2, itn, dA2), eA3 = fmaf(-dA3, itn, dA3);
        float eB0 = fmaf(-dB0, itn, dB0), eB1 = fmaf(-dB1, itn, dB1);
        float eB2 = fmaf(-dB2, itn, dB2), eB3 = fmaf(-dB3, itn, dB3);
        mA0 = fmaf(dA0, itn, mA0); mA1 = fmaf(dA1, itn, mA1);
        mA2 = fmaf(dA2, itn, mA2); mA3 = fmaf(dA3, itn, mA3);
        mB0 = fmaf(dB0, itn, mB0); mB1 = fmaf(dB1, itn, mB1);
        mB2 = fmaf(dB2, itn, mB2); mB3 = fmaf(dB3, itn, mB3);
        sA0 = fmaf(dA0, eA0, sA0); sA1 = fmaf(dA1, eA1, sA1);
        sA2 = fmaf(dA2, eA2, sA2); sA3 = fmaf(dA3, eA3, sA3);
        sB0 = fmaf(dB0, eB0, sB0); sB1 = fmaf(dB1, eB1, sB1);
        sB2 = fmaf(dB2, eB2, sB2); sB3 = fmaf(dB3, eB3, sB3);

        // ---- two independent butterflies, interleaved by stage ----
        float bnA = (sA0 + sA1) + (sA2 + sA3);
        float bnB = (sB0 + sB1) + (sB2 + sB3);
#pragma unroll
        for (int sft = 16; sft > 0; sft >>= 1) {
            bnA += __shfl_xor_sync(0xffffffffu, bnA, sft, 32);
            bnB += __shfl_xor_sync(0xffffffffu, bnB, sft, 32);
        }

        // ---- matvec for step t, both chains (q reused) ----
        const ulonglong2* zpA = (const ulonglong2*)sZ[t & 1][w][0];
        const ulonglong2* zpB = (const ulonglong2*)sZ[t & 1][w][1];
        unsigned long long aA0 = 0ull, aA1 = 0ull, aA2 = 0ull, aA3 = 0ull;
        unsigned long long aB0 = 0ull, aB1 = 0ull, aB2 = 0ull, aB3 = 0ull;
#pragma unroll
        for (int c = 0; c < 16; c++) {
            ulonglong2 xa = zpA[2 * c];
            ulonglong2 xc = zpA[2 * c + 1];
            ulonglong2 ya = zpB[2 * c];
            ulonglong2 yc = zpB[2 * c + 1];
            aA0 = fma2(xa.x, q[4 * c + 0], aA0);
            aB0 = fma2(ya.x, q[4 * c + 0], aB0);
            aA1 = fma2(xa.y, q[4 * c + 1], aA1);
            aB1 = fma2(ya.y, q[4 * c + 1], aB1);
            aA2 = fma2(xc.x, q[4 * c + 2], aA2);
            aB2 = fma2(yc.x, q[4 * c + 2], aB2);
            aA3 = fma2(xc.y, q[4 * c + 3], aA3);
            aB3 = fma2(yc.y, q[4 * c + 3], aB3);
        }
        unsigned long long tA = add2(add2(aA0, aA1), add2(aA2, aA3));
        unsigned long long tB = add2(add2(aB0, aB1), add2(aB2, aB3));
        float rAl, rAh, rBl, rBh;
        unpack2(tA, rAl, rAh);
        unpack2(tB, rBl, rBh);
        const float rA = rAl + rAh;
        const float rB = rBl + rBh;

        // ---- h EMA, log features ----
        hA = fmaf(rA, rA, GAMMA_C * hA);
        hB = fmaf(rB, rB, GAMMA_C * hB);
        const float xvA = __logf(fmaf(hA, cw, EPSH_C));
        const float xvB = __logf(fmaf(hB, cw, EPSH_C));
        oxA[(size_t)t * DOUTN] = xvA;
        oxB[(size_t)t * DOUTN] = xvB;
        const int tm = t & (TBLK - 1);
        xbA[lane * XPITCH + tm] = xvA;
        xbB[lane * XPITCH + tm] = xvB;

        // ---- deferred LN+classifier epilogue (every 32 steps, both chains) ----
        if (tm == (TBLK - 1)) {
            __syncwarp();
            const int tbase = t - (TBLK - 1);
            float sxA = 0.f, sx2A = 0.f, uA0 = 0.f, uA1 = 0.f, uA2 = 0.f, uA3 = 0.f;
            float sxB = 0.f, sx2B = 0.f, uB0 = 0.f, uB1 = 0.f, uB2 = 0.f, uB3 = 0.f;
#pragma unroll
            for (int j = 0; j < DOUTN; j++) {
                const float4 Aj = *(const float4*)&A[j][0];
                const float xjA = xbA[j * XPITCH + lane];
                const float xjB = xbB[j * XPITCH + lane];
                sxA += xjA;                sxB += xjB;
                sx2A = fmaf(xjA, xjA, sx2A); sx2B = fmaf(xjB, xjB, sx2B);
                uA0 = fmaf(xjA, Aj.x, uA0);  uB0 = fmaf(xjB, Aj.x, uB0);
                uA1 = fmaf(xjA, Aj.y, uA1);  uB1 = fmaf(xjB, Aj.y, uB1);
                uA2 = fmaf(xjA, Aj.z, uA2);  uB2 = fmaf(xjB, Aj.z, uB2);
                uA3 = fmaf(xjA, Aj.w, uA3);  uB3 = fmaf(xjB, Aj.w, uB3);
            }
            {
                const float mu  = sxA * (1.0f / 32.0f);
                const float var = fmaxf(fmaf(sx2A, 1.0f / 32.0f, -mu * mu), 0.0f);
                const float is  = rsqrtf(var + LNEPS_C);
                float4 lg;
                lg.x = fmaf(is, fmaf(-mu, Sa4.x, uA0), Sb4.x);
                lg.y = fmaf(is, fmaf(-mu, Sa4.y, uA1), Sb4.y);
                lg.z = fmaf(is, fmaf(-mu, Sa4.z, uA2), Sb4.z);
                lg.w = fmaf(is, fmaf(-mu, Sa4.w, uA3), Sb4.w);
                ((float4*)olA)[tbase + lane] = lg;
            }
            {
                const float mu  = sxB * (1.0f / 32.0f);
                const float var = fmaxf(fmaf(sx2B, 1.0f / 32.0f, -mu * mu), 0.0f);
                const float is  = rsqrtf(var + LNEPS_C);
                float4 lg;
                lg.x = fmaf(is, fmaf(-mu, Sa4.x, uB0), Sb4.x);
                lg.y = fmaf(is, fmaf(-mu, Sa4.y, uB1), Sb4.y);
                lg.z = fmaf(is, fmaf(-mu, Sa4.z, uB2), Sb4.z);
                lg.w = fmaf(is, fmaf(-mu, Sa4.w, uB3), Sb4.w);
                ((float4*)olB)[tbase + lane] = lg;
            }
        }

        // ---- produce z_tilde for step t+1, both chains ----
        {
            int tn = t + 1; if (tn > TT - 1) tn = TT - 1;
            const float4 C = cst[tn];
            cw = C.w;
            const float c2A = fmaf(bnA, C.y, EPS_C);
            const float c2B = fmaf(bnB, C.y, EPS_C);
            float4 ztA, ztB;
            ztA.x = eA0 * rsqrtf(fmaf(sA0, C.z, c2A));
            ztA.y = eA1 * rsqrtf(fmaf(sA1, C.z, c2A));
            ztA.z = eA2 * rsqrtf(fmaf(sA2, C.z, c2A));
            ztA.w = eA3 * rsqrtf(fmaf(sA3, C.z, c2A));
            ztB.x = eB0 * rsqrtf(fmaf(sB0, C.z, c2B));
            ztB.y = eB1 * rsqrtf(fmaf(sB1, C.z, c2B));
            ztB.z = eB2 * rsqrtf(fmaf(sB2, C.z, c2B));
            ztB.w = eB3 * rsqrtf(fmaf(sB3, C.z, c2B));
            ((float4*)sZ[(t + 1) & 1][w][0])[lane] = ztA;
            ((float4*)sZ[(t + 1) & 1][w][1])[lane] = ztB;
            __syncwarp();
        }
    }
}

extern "C" void kernel_launch(void* const* d_in, const int* in_sizes, int n_in,
                              void* d_out, int out_size) {
    const float* z_ticks = (const float*)d_in[0];
    const float* proj    = (const float*)d_in[1];
    const float* ln_w    = (const float*)d_in[2];
    const float* ln_b    = (const float*)d_in[3];
    const float* cls_w   = (const float*)d_in[4];
    const float* cls_b   = (const float*)d_in[5];

    float* out_x      = (float*)d_out;
    float* out_logits = out_x + (size_t)BATCH * TT * DOUTN;

    sync_head_kernel<<<BATCH / 4, 64>>>(z_ticks, proj, ln_w, ln_b,
                                        cls_w, cls_b, out_x, out_logits);
}

// round 10
// speedup vs baseline: 1.1581x; 1.1581x over previous
#include <cuda_runtime.h>
#include <cstddef>

#define BATCH 512
#define TT    512
#define DD    128
#define DOUTN 32
#define CCLS  4
#define TBLK  32
#define XPITCH 33

#define ALPHA_C 0.1f
#define GAMMA_C 0.9f
#define EPS_C   1e-5f
#define EPSH_C  1e-6f
#define LNEPS_C 1e-5f

__device__ __forceinline__ float warp_sum(float v) {
#pragma unroll
    for (int s = 16; s > 0; s >>= 1)
        v += __shfl_xor_sync(0xffffffffu, v, s, 32);
    return v;
}

__device__ __forceinline__ unsigned long long fma2(unsigned long long a,
                                                   unsigned long long b,
                                                   unsigned long long c) {
    unsigned long long d;
    asm("fma.rn.f32x2 %0, %1, %2, %3;" : "=l"(d) : "l"(a), "l"(b), "l"(c));
    return d;
}

__device__ __forceinline__ unsigned long long add2(unsigned long long a,
                                                   unsigned long long b) {
    unsigned long long d;
    asm("add.rn.f32x2 %0, %1, %2;" : "=l"(d) : "l"(a), "l"(b));
    return d;
}

__device__ __forceinline__ unsigned long long pack2(float lo, float hi) {
    unsigned long long r;
    asm("mov.b64 %0, {%1, %2};" : "=l"(r) : "f"(lo), "f"(hi));
    return r;
}

__device__ __forceinline__ void unpack2(unsigned long long v, float& lo, float& hi) {
    asm("mov.b64 {%0, %1}, %2;" : "=f"(lo), "=f"(hi) : "l"(v));
}

__device__ __forceinline__ void pair_bar(int id) {
    asm volatile("bar.sync %0, 64;" :: "r"(id) : "memory");
}

__global__ __launch_bounds__(256, 1)
void sync_head_kernel(const float* __restrict__ z_ticks,
                      const float* __restrict__ proj,
                      const float* __restrict__ ln_w,
                      const float* __restrict__ ln_b,
                      const float* __restrict__ cls_w,
                      const float* __restrict__ cls_b,
                      float* __restrict__ out_x,
                      float* __restrict__ out_logits) {
    __shared__ __align__(16) float sZ[4][2][DD];     // [pair][buf][d]
    __shared__ float4 cst[TT];       // (pad, alpha*inv_denom/128, (1-alpha)*inv_denom, inv_s)
    __shared__ float itab[TT + 1];   // 1/(t+1)
    __shared__ __align__(16) float A[DOUTN][CCLS];
    __shared__ float4 SaV, SbV;
    __shared__ float xbuf[4][DOUTN * XPITCH];

    const int lane = threadIdx.x & 31;
    const int w    = threadIdx.x >> 5;

    // ---- tables (all 256 threads) ----
    for (int t = threadIdx.x; t <= TT; t += 256) {
        float tau = (float)(t + 1);
        itab[t] = 1.0f / tau;
        if (t < TT) {
            float denom = fmaxf(tau - 1.0f, 1.0f);
            float inv_denom = 1.0f / denom;
            float g = __powf(GAMMA_C, tau);
            float s = (1.0f - g) / (1.0f - GAMMA_C);
            cst[t] = make_float4(0.0f,
                                 ALPHA_C * inv_denom * (1.0f / 128.0f),
                                 (1.0f - ALPHA_C) * inv_denom,
                                 1.0f / s);
        }
    }
    if (threadIdx.x < DOUTN * CCLS) {
        int j = threadIdx.x >> 2, c = threadIdx.x & 3;
        A[j][c] = ln_w[j] * cls_w[c * DOUTN + j];
    }
    if (threadIdx.x < 2 * CCLS) {
        int c = threadIdx.x & 3;
        float acc = 0.f;
        if (threadIdx.x < CCLS) {
            for (int j = 0; j < DOUTN; j++) acc += ln_w[j] * cls_w[c * DOUTN + j];
            ((float*)&SaV)[c] = acc;
        } else {
            for (int j = 0; j < DOUTN; j++) acc += ln_b[j] * cls_w[c * DOUTN + j];
            ((float*)&SbV)[c] = acc + cls_b[c];
        }
    }
    __syncthreads();

    if (w < 4) {
        // ================= PRODUCER warp: pair w =================
        const int pair  = w;
        const int batch = blockIdx.x * 4 + pair;
        const int barid = 1 + pair;
        const float* zptr = z_ticks + (size_t)batch * TT * DD + lane * 4;

        float4 z0 = *(const float4*)(zptr);
        float m0 = z0.x, m1 = z0.y, m2_ = z0.z, m3 = z0.w;
        float s0 = 0.f, s1 = 0.f, s2 = 0.f, s3 = 0.f;

        // z_tilde_0 = 0
        ((float4*)sZ[pair][0])[lane] = make_float4(0.f, 0.f, 0.f, 0.f);

        float4 zb0 = *(const float4*)(zptr + DD);
        float4 zb1 = *(const float4*)(zptr + 2 * DD);

#pragma unroll 1
        for (int t = 0; t < TT; t++) {
            pair_bar(barid);   // publish z_tilde_t; buffer (t+1)&1 is free

            const float4 z = zb0;
            zb0 = zb1;
            {
                int tp = t + 3; if (tp > TT - 1) tp = TT - 1;
                zb1 = *(const float4*)(zptr + (size_t)tp * DD);
            }
            const float itn = itab[t + 1];
            float d0 = z.x - m0, d1 = z.y - m1, d2 = z.z - m2_, d3 = z.w - m3;
            float e0 = fmaf(-d0, itn, d0);
            float e1 = fmaf(-d1, itn, d1);
            float e2 = fmaf(-d2, itn, d2);
            float e3 = fmaf(-d3, itn, d3);
            m0 = fmaf(d0, itn, m0);
            m1 = fmaf(d1, itn, m1);
            m2_ = fmaf(d2, itn, m2_);
            m3 = fmaf(d3, itn, m3);
            s0 = fmaf(d0, e0, s0);
            s1 = fmaf(d1, e1, s1);
            s2 = fmaf(d2, e2, s2);
            s3 = fmaf(d3, e3, s3);
            const float bn = warp_sum((s0 + s1) + (s2 + s3));

            int tn = t + 1; if (tn > TT - 1) tn = TT - 1;
            const float4 C = cst[tn];
            const float c2 = fmaf(bn, C.y, EPS_C);
            float4 zt;
            zt.x = e0 * rsqrtf(fmaf(s0, C.z, c2));
            zt.y = e1 * rsqrtf(fmaf(s1, C.z, c2));
            zt.z = e2 * rsqrtf(fmaf(s2, C.z, c2));
            zt.w = e3 * rsqrtf(fmaf(s3, C.z, c2));
            ((float4*)sZ[pair][(t + 1) & 1])[lane] = zt;
        }
        // final bar so the consumer's last iteration can pass its barrier
        // (consumer at t=TT-1 waits on the bar we issue at t=TT-1 above; no
        // extra needed — loop counts match.)
    } else {
        // ================= CONSUMER warp: pair (w+3)&3 (different SMSP) ====
        const int pair  = (w + 3) & 3;
        const int batch = blockIdx.x * 4 + pair;
        const int barid = 1 + pair;

        // proj column `lane` in registers
        unsigned long long q[DD / 2];
#pragma unroll
        for (int i = 0; i < DD / 2; i++) {
            float a = proj[(2 * i) * DOUTN + lane];
            float b = proj[(2 * i + 1) * DOUTN + lane];
            q[i] = pack2(a, b);
        }
        const float4 Sa4 = SaV;
        const float4 Sb4 = SbV;

        float* ox  = out_x + ((size_t)batch * TT) * DOUTN + lane;
        float* olb = out_logits + (size_t)batch * TT * CCLS;
        float* xb  = xbuf[pair];
        float h = 0.f;

#pragma unroll 1
        for (int t = 0; t < TT; t++) {
            pair_bar(barid);   // z_tilde_t is ready in sZ[pair][t&1]

            const float cw = cst[t].w;
            const ulonglong2* zp = (const ulonglong2*)sZ[pair][t & 1];
            unsigned long long acc0 = 0ull, acc1 = 0ull, acc2 = 0ull, acc3 = 0ull;
#pragma unroll
            for (int c = 0; c < 16; c++) {
                ulonglong2 za = zp[2 * c];
                ulonglong2 zc = zp[2 * c + 1];
                acc0 = fma2(za.x, q[4 * c + 0], acc0);
                acc1 = fma2(za.y, q[4 * c + 1], acc1);
                acc2 = fma2(zc.x, q[4 * c + 2], acc2);
                acc3 = fma2(zc.y, q[4 * c + 3], acc3);
            }
            unsigned long long sT = add2(add2(acc0, acc1), add2(acc2, acc3));
            float rlo, rhi;
            unpack2(sT, rlo, rhi);
            const float r = rlo + rhi;

            h = fmaf(r, r, GAMMA_C * h);
            const float xv = __logf(fmaf(h, cw, EPSH_C));
            ox[(size_t)t * DOUTN] = xv;
            const int tm = t & (TBLK - 1);
            xb[lane * XPITCH + tm] = xv;

            if (tm == (TBLK - 1)) {
                __syncwarp();       // all lanes' xbuf writes visible
                const int tbase = t - (TBLK - 1);
                float sx = 0.f, sx2 = 0.f;
                float dt0 = 0.f, dt1 = 0.f, dt2 = 0.f, dt3 = 0.f;
#pragma unroll
                for (int j = 0; j < DOUTN; j++) {
                    const float xj = xb[j * XPITCH + lane];
                    const float4 Aj = *(const float4*)&A[j][0];
                    sx  += xj;
                    sx2 = fmaf(xj, xj, sx2);
                    dt0 = fmaf(xj, Aj.x, dt0);
                    dt1 = fmaf(xj, Aj.y, dt1);
                    dt2 = fmaf(xj, Aj.z, dt2);
                    dt3 = fmaf(xj, Aj.w, dt3);
                }
                const float mu      = sx * (1.0f / 32.0f);
                const float var     = fmaxf(fmaf(sx2, 1.0f / 32.0f, -mu * mu), 0.0f);
                const float inv_std = rsqrtf(var + LNEPS_C);
                float4 lg;
                lg.x = fmaf(inv_std, fmaf(-mu, Sa4.x, dt0), Sb4.x);
                lg.y = fmaf(inv_std, fmaf(-mu, Sa4.y, dt1), Sb4.y);
                lg.z = fmaf(inv_std, fmaf(-mu, Sa4.z, dt2), Sb4.z);
                lg.w = fmaf(inv_std, fmaf(-mu, Sa4.w, dt3), Sb4.w);
                ((float4*)olb)[tbase + lane] = lg;
                __syncwarp();       // xbuf WAR before next iteration's writes
            }
        }
    }
}

extern "C" void kernel_launch(void* const* d_in, const int* in_sizes, int n_in,
                              void* d_out, int out_size) {
    const float* z_ticks = (const float*)d_in[0];
    const float* proj    = (const float*)d_in[1];
    const float* ln_w    = (const float*)d_in[2];
    const float* ln_b    = (const float*)d_in[3];
    const float* cls_w   = (const float*)d_in[4];
    const float* cls_b   = (const float*)d_in[5];

    float* out_x      = (float*)d_out;
    float* out_logits = out_x + (size_t)BATCH * TT * DOUTN;

    sync_head_kernel<<<BATCH / 4, 256>>>(z_ticks, proj, ln_w, ln_b,
                                         cls_w, cls_b, out_x, out_logits);
}

// round 11
// speedup vs baseline: 1.5987x; 1.3804x over previous
#include <cuda_runtime.h>
#include <cstddef>

#define BATCH 512
#define TT    512
#define DD    128
#define DOUTN 32
#define CCLS  4
#define TBLK  32
#define XPITCH 33
#define NW    8            // warps (= batches) per block

#define ALPHA_C 0.1f
#define GAMMA_C 0.9f
#define EPS_C   1e-5f
#define EPSH_C  1e-6f
#define LNEPS_C 1e-5f

__device__ __forceinline__ float warp_sum(float v) {
#pragma unroll
    for (int s = 16; s > 0; s >>= 1)
        v += __shfl_xor_sync(0xffffffffu, v, s, 32);
    return v;
}

__device__ __forceinline__ unsigned long long fma2(unsigned long long a,
                                                   unsigned long long b,
                                                   unsigned long long c) {
    unsigned long long d;
    asm("fma.rn.f32x2 %0, %1, %2, %3;" : "=l"(d) : "l"(a), "l"(b), "l"(c));
    return d;
}

__device__ __forceinline__ unsigned long long add2(unsigned long long a,
                                                   unsigned long long b) {
    unsigned long long d;
    asm("add.rn.f32x2 %0, %1, %2;" : "=l"(d) : "l"(a), "l"(b));
    return d;
}

__device__ __forceinline__ unsigned long long pack2(float lo, float hi) {
    unsigned long long r;
    asm("mov.b64 %0, {%1, %2};" : "=l"(r) : "f"(lo), "f"(hi));
    return r;
}

__device__ __forceinline__ void unpack2(unsigned long long v, float& lo, float& hi) {
    asm("mov.b64 {%0, %1}, %2;" : "=f"(lo), "=f"(hi) : "l"(v));
}

__global__ __launch_bounds__(32 * NW, 1)
void sync_head_kernel(const float* __restrict__ z_ticks,
                      const float* __restrict__ proj,
                      const float* __restrict__ ln_w,
                      const float* __restrict__ ln_b,
                      const float* __restrict__ cls_w,
                      const float* __restrict__ cls_b,
                      float* __restrict__ out_x,
                      float* __restrict__ out_logits) {
    __shared__ __align__(16) float sZ[2][NW][DD];
    __shared__ float4 cst[TT];      // (pad, alpha*inv_denom/128, (1-alpha)*inv_denom, inv_s)
    __shared__ float itab[TT + 1];  // 1/(t+1)
    __shared__ __align__(16) float A[DOUTN][CCLS];
    __shared__ float4 SaV, SbV;
    __shared__ float xbuf[NW][DOUTN * XPITCH];

    const int lane  = threadIdx.x & 31;
    const int w     = threadIdx.x >> 5;
    const int batch = blockIdx.x * NW + w;

    for (int t = threadIdx.x; t <= TT; t += 32 * NW) {
        float tau = (float)(t + 1);
        itab[t] = 1.0f / tau;
        if (t < TT) {
            float denom = fmaxf(tau - 1.0f, 1.0f);
            float inv_denom = 1.0f / denom;
            float g = __powf(GAMMA_C, tau);
            float s = (1.0f - g) / (1.0f - GAMMA_C);
            cst[t] = make_float4(0.0f,
                                 ALPHA_C * inv_denom * (1.0f / 128.0f),
                                 (1.0f - ALPHA_C) * inv_denom,
                                 1.0f / s);
        }
    }
    if (threadIdx.x < DOUTN * CCLS) {
        int j = threadIdx.x >> 2, c = threadIdx.x & 3;
        A[j][c] = ln_w[j] * cls_w[c * DOUTN + j];
    }
    if (threadIdx.x < 2 * CCLS) {
        int c = threadIdx.x & 3;
        float acc = 0.f;
        if (threadIdx.x < CCLS) {
            for (int j = 0; j < DOUTN; j++) acc += ln_w[j] * cls_w[c * DOUTN + j];
            ((float*)&SaV)[c] = acc;
        } else {
            for (int j = 0; j < DOUTN; j++) acc += ln_b[j] * cls_w[c * DOUTN + j];
            ((float*)&SbV)[c] = acc + cls_b[c];
        }
    }

    unsigned long long q[DD / 2];
#pragma unroll
    for (int i = 0; i < DD / 2; i++) {
        float a = proj[(2 * i) * DOUTN + lane];
        float b = proj[(2 * i + 1) * DOUTN + lane];
        q[i] = pack2(a, b);
    }

    __syncthreads();
    const float4 Sa4 = SaV;
    const float4 Sb4 = SbV;

    const float* zptr = z_ticks + (size_t)batch * TT * DD + lane * 4;
    float* ox  = out_x + ((size_t)batch * TT) * DOUTN + lane;
    float* olb = out_logits + (size_t)batch * TT * CCLS;
    float* xb  = xbuf[w];

    // ---- preamble: state after step 0 (m = z0, s = 0); z_tilde_0 = 0 ----
    float4 z0 = *(const float4*)(zptr);
    float m0 = z0.x, m1 = z0.y, m2_ = z0.z, m3 = z0.w;
    float s0 = 0.f, s1 = 0.f, s2 = 0.f, s3 = 0.f;
    float h = 0.f;
    float cw = cst[0].w;

    ((float4*)sZ[0][w])[lane] = make_float4(0.f, 0.f, 0.f, 0.f);
    __syncwarp();

    float4 zb0 = *(const float4*)(zptr + DD);
    float4 zb1 = *(const float4*)(zptr + 2 * DD);

#pragma unroll 2
    for (int t = 0; t < TT; t++) {
        // ---- Welford for step t+1 ----
        const float4 z = zb0;
        zb0 = zb1;
        {
            int tp = t + 3; if (tp > TT - 1) tp = TT - 1;
            zb1 = *(const float4*)(zptr + (size_t)tp * DD);
        }
        const float itn = itab[t + 1];
        float d0 = z.x - m0, d1 = z.y - m1, d2 = z.z - m2_, d3 = z.w - m3;
        float e0 = fmaf(-d0, itn, d0);
        float e1 = fmaf(-d1, itn, d1);
        float e2 = fmaf(-d2, itn, d2);
        float e3 = fmaf(-d3, itn, d3);
        m0 = fmaf(d0, itn, m0);
        m1 = fmaf(d1, itn, m1);
        m2_ = fmaf(d2, itn, m2_);
        m3 = fmaf(d3, itn, m3);
        s0 = fmaf(d0, e0, s0);
        s1 = fmaf(d1, e1, s1);
        s2 = fmaf(d2, e2, s2);
        s3 = fmaf(d3, e3, s3);
        const float bn = warp_sum((s0 + s1) + (s2 + s3));

        // ---- matvec for step t ----
        const ulonglong2* zp = (const ulonglong2*)sZ[t & 1][w];
        unsigned long long acc0 = 0ull, acc1 = 0ull, acc2 = 0ull, acc3 = 0ull;
#pragma unroll
        for (int c = 0; c < 16; c++) {
            ulonglong2 za = zp[2 * c];
            ulonglong2 zc = zp[2 * c + 1];
            acc0 = fma2(za.x, q[4 * c + 0], acc0);
            acc1 = fma2(za.y, q[4 * c + 1], acc1);
            acc2 = fma2(zc.x, q[4 * c + 2], acc2);
            acc3 = fma2(zc.y, q[4 * c + 3], acc3);
        }
        unsigned long long sT = add2(add2(acc0, acc1), add2(acc2, acc3));
        float rlo, rhi;
        unpack2(sT, rlo, rhi);
        const float r = rlo + rhi;

        // ---- h EMA, log feature ----
        h = fmaf(r, r, GAMMA_C * h);
        const float xv = __logf(fmaf(h, cw, EPSH_C));
        ox[(size_t)t * DOUTN] = xv;
        xb[lane * XPITCH + (t & (TBLK - 1))] = xv;

        // ---- deferred LN+classifier epilogue (every 32 steps) ----
        if ((t & (TBLK - 1)) == (TBLK - 1)) {
            __syncwarp();
            const int tbase = t - (TBLK - 1);
            float sx = 0.f, sx2 = 0.f;
            float dt0 = 0.f, dt1 = 0.f, dt2 = 0.f, dt3 = 0.f;
#pragma unroll
            for (int j = 0; j < DOUTN; j++) {
                const float xj = xb[j * XPITCH + lane];
                const float4 Aj = *(const float4*)&A[j][0];
                sx  += xj;
                sx2 = fmaf(xj, xj, sx2);
                dt0 = fmaf(xj, Aj.x, dt0);
                dt1 = fmaf(xj, Aj.y, dt1);
                dt2 = fmaf(xj, Aj.z, dt2);
                dt3 = fmaf(xj, Aj.w, dt3);
            }
            const float mu      = sx * (1.0f / 32.0f);
            const float var     = fmaxf(fmaf(sx2, 1.0f / 32.0f, -mu * mu), 0.0f);
            const float inv_std = rsqrtf(var + LNEPS_C);
            float4 lg;
            lg.x = fmaf(inv_std, fmaf(-mu, Sa4.x, dt0), Sb4.x);
            lg.y = fmaf(inv_std, fmaf(-mu, Sa4.y, dt1), Sb4.y);
            lg.z = fmaf(inv_std, fmaf(-mu, Sa4.z, dt2), Sb4.z);
            lg.w = fmaf(inv_std, fmaf(-mu, Sa4.w, dt3), Sb4.w);
            ((float4*)olb)[tbase + lane] = lg;
        }

        // ---- produce z_tilde for step t+1 ----
        {
            int tn = t + 1; if (tn > TT - 1) tn = TT - 1;
            const float4 C = cst[tn];
            cw = C.w;
            const float c2 = fmaf(bn, C.y, EPS_C);
            float4 zt;
            zt.x = e0 * rsqrtf(fmaf(s0, C.z, c2));
            zt.y = e1 * rsqrtf(fmaf(s1, C.z, c2));
            zt.z = e2 * rsqrtf(fmaf(s2, C.z, c2));
            zt.w = e3 * rsqrtf(fmaf(s3, C.z, c2));
            ((float4*)sZ[(t + 1) & 1][w])[lane] = zt;
            __syncwarp();
        }
    }
}

extern "C" void kernel_launch(void* const* d_in, const int* in_sizes, int n_in,
                              void* d_out, int out_size) {
    const float* z_ticks = (const float*)d_in[0];
    const float* proj    = (const float*)d_in[1];
    const float* ln_w    = (const float*)d_in[2];
    const float* ln_b    = (const float*)d_in[3];
    const float* cls_w   = (const float*)d_in[4];
    const float* cls_b   = (const float*)d_in[5];

    float* out_x      = (float*)d_out;
    float* out_logits = out_x + (size_t)BATCH * TT * DOUTN;

    sync_head_kernel<<<BATCH / NW, 32 * NW>>>(z_ticks, proj, ln_w, ln_b,
                                              cls_w, cls_b, out_x, out_logits);
}